// round 13
// baseline (speedup 1.0000x reference)
#include <cuda_runtime.h>
#include <cuda_bf16.h>
#include <cstdint>

#define B_ 2048
#define T_ 18
#define C_ 128
#define D_ 4096
#define P_ 32
#define NT 19               // 18 timesteps + pw1 block
#define NUNITS 640          // 10 tb-pairs * 16 rt * 2 nh * 2 kh
#define NPCTAS 296

// ---------------- scratch (device globals; no allocation allowed) ----------
__device__ float g_h   [B_ * C_];
__device__ float g_mean[C_];
__device__ float g_rstd[C_];
__device__ float g_nce;
__device__ int   g_work;

// fp32 partial accumulators for the K-split GEMM: [t][b][c]
__device__ __align__(16) float g_acc0[NT * B_ * C_];
__device__ __align__(16) float g_acc1[NT * B_ * C_];

// mma-fragment-packed operands.
// A: [rt 0..15][k16 0..255][m16 0..7][lane 0..31] -> uint4 (a0,a1,a2,a3)
// W: [t 0..18][k16 0..255][n16grp 0..7][lane]     -> uint4 (blk0 b0,b1, blk1 b0,b1)
__device__ __align__(16) uint4 g_Afh[16 * 256 * 8 * 32];
__device__ __align__(16) uint4 g_Afl[16 * 256 * 8 * 32];
__device__ __align__(16) uint4 g_Wfh[NT * 256 * 8 * 32];
__device__ __align__(16) uint4 g_Wfl[NT * 256 * 8 * 32];

// bf16 hi/lo enc + pred for flash: [t][b][c] row-major (C=128)
__device__ __align__(16) __nv_bfloat16 g_Ehi[T_ * B_ * C_];
__device__ __align__(16) __nv_bfloat16 g_Elo[T_ * B_ * C_];
__device__ __align__(16) __nv_bfloat16 g_Phi[T_ * B_ * C_];
__device__ __align__(16) __nv_bfloat16 g_Plo[T_ * B_ * C_];

// ---------------- helpers ---------------------------------------------------
__device__ __forceinline__ uint32_t smem_u32(const void* p) {
    uint32_t a;
    asm("{ .reg .u64 t; cvta.to.shared.u64 t, %1; cvt.u32.u64 %0, t; }"
        : "=r"(a) : "l"(p));
    return a;
}

__device__ __forceinline__ void cp16(uint32_t dst, const void* src) {
    asm volatile("cp.async.cg.shared.global [%0], [%1], 16;"
                 :: "r"(dst), "l"(src) : "memory");
}
#define CP_COMMIT() asm volatile("cp.async.commit_group;" ::: "memory")
#define CP_WAIT(N)  asm volatile("cp.async.wait_group %0;" :: "n"(N) : "memory")

__device__ __forceinline__ void ldmx4(uint32_t* r, uint32_t addr) {
    asm volatile("ldmatrix.sync.aligned.m8n8.x4.shared.b16 {%0,%1,%2,%3}, [%4];"
                 : "=r"(r[0]), "=r"(r[1]), "=r"(r[2]), "=r"(r[3]) : "r"(addr));
}

__device__ __forceinline__ void mma_bf16(float* c, const uint32_t* a,
                                         const uint32_t* b) {
    asm volatile(
        "mma.sync.aligned.m16n8k16.row.col.f32.bf16.bf16.f32 "
        "{%0,%1,%2,%3}, {%4,%5,%6,%7}, {%8,%9}, {%0,%1,%2,%3};"
        : "+f"(c[0]), "+f"(c[1]), "+f"(c[2]), "+f"(c[3])
        : "r"(a[0]), "r"(a[1]), "r"(a[2]), "r"(a[3]), "r"(b[0]), "r"(b[1]));
}

__device__ __forceinline__ uint32_t pack_bf16(float x, float y) {
    __nv_bfloat162 v;
    v.x = __float2bfloat16(x);
    v.y = __float2bfloat16(y);
    return *(uint32_t*)&v;
}
__device__ __forceinline__ void hilo_pack(float x, float y,
                                          uint32_t& h, uint32_t& l) {
    __nv_bfloat16 hx = __float2bfloat16(x);
    __nv_bfloat16 hy = __float2bfloat16(y);
    h = pack_bf16(x, y);
    l = pack_bf16(x - __bfloat162float(hx), y - __bfloat162float(hy));
}

// ---------------- init: z_aug2 [B,C,T] -> Ehi/Elo [T,B,C]; zero nce/work ---
__global__ void init_kernel(const float* __restrict__ z)
{
    int bc = blockIdx.x * blockDim.x + threadIdx.x;
    if (bc == 0) { g_nce = 0.0f; g_work = 0; }
    if (bc < B_ * C_) {
        const float* src = z + (size_t)bc * T_;
#pragma unroll
        for (int t = 0; t < T_; t++) {
            float v = src[t];
            __nv_bfloat16 hi = __float2bfloat16(v);
            __nv_bfloat16 lo = __float2bfloat16(v - __bfloat162float(hi));
            g_Ehi[(size_t)t * B_ * C_ + bc] = hi;
            g_Elo[(size_t)t * B_ * C_ + bc] = lo;
        }
    }
}

// ---------------- pack A (c_t) into mma A-fragment layout -------------------
__global__ void convA_kernel(const float* __restrict__ A)
{
    int id = blockIdx.x * 256 + threadIdx.x;      // 0 .. 1048575
    int lane = id & 31;
    int b = id >> 5;                               // 0 .. 32767
    int mi = b & 7, kg = (b >> 3) & 255, rt = b >> 11;
    int row = rt * 128 + mi * 16 + (lane >> 2);
    int k   = kg * 16 + (lane & 3) * 2;

    const float* r0 = A + (size_t)row * D_ + k;
    const float* r1 = r0 + 8 * D_;
    uint4 h, l;
    hilo_pack(r0[0], r0[1], h.x, l.x);
    hilo_pack(r1[0], r1[1], h.y, l.y);
    hilo_pack(r0[8], r0[9], h.z, l.z);
    hilo_pack(r1[8], r1[9], h.w, l.w);
    g_Afh[(size_t)b * 32 + lane] = h;
    g_Afl[(size_t)b * 32 + lane] = l;
}

// ---------------- pack W (Wk_w + pw1) into mma B-fragment layout ------------
__global__ void convW_kernel(const float* __restrict__ Wk_w,
                             const float* __restrict__ pw1)
{
    int id = blockIdx.x * 256 + threadIdx.x;      // 0 .. 1245183
    int lane = id & 31;
    int b = id >> 5;                               // 0 .. 38911
    int g = b & 7, kg = (b >> 3) & 255, t = b >> 11;
    int n0 = g * 16 + (lane >> 2);
    int k  = kg * 16 + (lane & 3) * 2;

    const float* s0 = (t < T_) ? (Wk_w + ((size_t)t * C_ + n0) * D_ + k)
                               : (pw1 + (size_t)n0 * D_ + k);
    const float* s1 = s0 + 8 * D_;
    uint4 h, l;
    hilo_pack(s0[0], s0[1], h.x, l.x);
    hilo_pack(s0[8], s0[9], h.y, l.y);
    hilo_pack(s1[0], s1[1], h.z, l.z);
    hilo_pack(s1[8], s1[9], h.w, l.w);
    g_Wfh[(size_t)b * 32 + lane] = h;
    g_Wfl[(size_t)b * 32 + lane] = l;
}

// ---------------- persistent mma.sync GEMM, 2 timesteps per unit ------------
// unit u: tp = u>>6 (tb pair); r6 = u&63: kh = r6&1, nh = (r6>>1)&1, rt = r6>>2
// tb0 = 2*tp, tb1 = 2*tp+1 (tb1 may be absent when == NT).
// A fragments loaded once per k-step feed BOTH timesteps (1.5x less L2/MMA).
__global__ __launch_bounds__(256, 2) void gemm_mma_kernel()
{
    __shared__ int s_u;
    const int tid = threadIdx.x;
    const int lane = tid & 31, wid = tid >> 5;
    const int wm = wid >> 1, wn = wid & 1;     // warp tile 32x32

    for (;;) {
        __syncthreads();
        if (tid == 0) s_u = atomicAdd(&g_work, 1);
        __syncthreads();
        const int u = s_u;
        if (u >= NUNITS) break;

        const int tp = u >> 6;
        const int r6 = u & 63;
        const int kh = r6 & 1;
        const int nh = (r6 >> 1) & 1;
        const int rt = r6 >> 2;
        const int tb0 = 2 * tp;
        const int tb1 = tb0 + 1;
        const bool has1 = (tb1 < NT);

        float acc0[2][4][4], acc1[2][4][4];
#pragma unroll
        for (int mi = 0; mi < 2; mi++)
#pragma unroll
            for (int ni = 0; ni < 4; ni++)
#pragma unroll
                for (int q = 0; q < 4; q++) {
                    acc0[mi][ni][q] = 0.0f;
                    acc1[mi][ni][q] = 0.0f;
                }

        const uint4* pAh = g_Afh +
            ((size_t)(rt * 256 + kh * 128) * 8 + 2 * wm) * 32 + lane;
        const uint4* pAl = g_Afl +
            ((size_t)(rt * 256 + kh * 128) * 8 + 2 * wm) * 32 + lane;
        const uint4* pW0h = g_Wfh +
            ((size_t)(tb0 * 256 + kh * 128) * 8 + nh * 4 + wn * 2) * 32 + lane;
        const uint4* pW0l = g_Wfl +
            ((size_t)(tb0 * 256 + kh * 128) * 8 + nh * 4 + wn * 2) * 32 + lane;
        const uint4* pW1h = g_Wfh +
            ((size_t)((has1 ? tb1 : tb0) * 256 + kh * 128) * 8 + nh * 4 + wn * 2) * 32 + lane;
        const uint4* pW1l = g_Wfl +
            ((size_t)((has1 ? tb1 : tb0) * 256 + kh * 128) * 8 + nh * 4 + wn * 2) * 32 + lane;

#pragma unroll 1
        for (int kg = 0; kg < 128; kg++) {
            uint32_t ah[8], al[8];
            {
                uint4 v;
                v = pAh[0];  ah[0] = v.x; ah[1] = v.y; ah[2] = v.z; ah[3] = v.w;
                v = pAh[32]; ah[4] = v.x; ah[5] = v.y; ah[6] = v.z; ah[7] = v.w;
                v = pAl[0];  al[0] = v.x; al[1] = v.y; al[2] = v.z; al[3] = v.w;
                v = pAl[32]; al[4] = v.x; al[5] = v.y; al[6] = v.z; al[7] = v.w;
            }
            pAh += 256; pAl += 256;

            {   // timestep tb0
                uint32_t wh[8], wl[8];
                uint4 v;
                v = pW0h[0];  wh[0] = v.x; wh[1] = v.y; wh[2] = v.z; wh[3] = v.w;
                v = pW0h[32]; wh[4] = v.x; wh[5] = v.y; wh[6] = v.z; wh[7] = v.w;
                v = pW0l[0];  wl[0] = v.x; wl[1] = v.y; wl[2] = v.z; wl[3] = v.w;
                v = pW0l[32]; wl[4] = v.x; wl[5] = v.y; wl[6] = v.z; wl[7] = v.w;
                pW0h += 256; pW0l += 256;
#pragma unroll
                for (int mi = 0; mi < 2; mi++) {
#pragma unroll
                    for (int ni = 0; ni < 4; ni++)
                        mma_bf16(acc0[mi][ni], ah + mi * 4, wh + ni * 2);
#pragma unroll
                    for (int ni = 0; ni < 4; ni++)
                        mma_bf16(acc0[mi][ni], ah + mi * 4, wl + ni * 2);
#pragma unroll
                    for (int ni = 0; ni < 4; ni++)
                        mma_bf16(acc0[mi][ni], al + mi * 4, wh + ni * 2);
                }
            }
            if (has1) {   // timestep tb1
                uint32_t wh[8], wl[8];
                uint4 v;
                v = pW1h[0];  wh[0] = v.x; wh[1] = v.y; wh[2] = v.z; wh[3] = v.w;
                v = pW1h[32]; wh[4] = v.x; wh[5] = v.y; wh[6] = v.z; wh[7] = v.w;
                v = pW1l[0];  wl[0] = v.x; wl[1] = v.y; wl[2] = v.z; wl[3] = v.w;
                v = pW1l[32]; wl[4] = v.x; wl[5] = v.y; wl[6] = v.z; wl[7] = v.w;
#pragma unroll
                for (int mi = 0; mi < 2; mi++) {
#pragma unroll
                    for (int ni = 0; ni < 4; ni++)
                        mma_bf16(acc1[mi][ni], ah + mi * 4, wh + ni * 2);
#pragma unroll
                    for (int ni = 0; ni < 4; ni++)
                        mma_bf16(acc1[mi][ni], ah + mi * 4, wl + ni * 2);
#pragma unroll
                    for (int ni = 0; ni < 4; ni++)
                        mma_bf16(acc1[mi][ni], al + mi * 4, wh + ni * 2);
                }
            }
            pW1h += 256; pW1l += 256;
        }

        // ---- epilogue: fp32 partial store (disjoint per kh) ----
        float* base = kh ? g_acc1 : g_acc0;
        const int r0 = rt * 128 + wm * 32 + (lane >> 2);
        const int c0 = nh * 64 + wn * 32 + (lane & 3) * 2;
        {
            float* outp = base + (size_t)tb0 * B_ * C_;
#pragma unroll
            for (int mi = 0; mi < 2; mi++)
#pragma unroll
                for (int ni = 0; ni < 4; ni++) {
                    int row = r0 + mi * 16, col = c0 + ni * 8;
                    float2 v;
                    v.x = acc0[mi][ni][0]; v.y = acc0[mi][ni][1];
                    *(float2*)(outp + (size_t)row * C_ + col) = v;
                    v.x = acc0[mi][ni][2]; v.y = acc0[mi][ni][3];
                    *(float2*)(outp + (size_t)(row + 8) * C_ + col) = v;
                }
        }
        if (has1) {
            float* outp = base + (size_t)tb1 * B_ * C_;
#pragma unroll
            for (int mi = 0; mi < 2; mi++)
#pragma unroll
                for (int ni = 0; ni < 4; ni++) {
                    int row = r0 + mi * 16, col = c0 + ni * 8;
                    float2 v;
                    v.x = acc1[mi][ni][0]; v.y = acc1[mi][ni][1];
                    *(float2*)(outp + (size_t)row * C_ + col) = v;
                    v.x = acc1[mi][ni][2]; v.y = acc1[mi][ni][3];
                    *(float2*)(outp + (size_t)(row + 8) * C_ + col) = v;
                }
        }
    }
}

// ---------------- combine: acc0+acc1+bias -> Phi/Plo (t<18) or g_h ---------
__global__ void combine_kernel(const float* __restrict__ Wk_b,
                               const float* __restrict__ pb1)
{
    const int per_t = B_ * C_ / 4;
    int i = blockIdx.x * 256 + threadIdx.x;
    int t = i / per_t;
    int r = i - t * per_t;
    int c = (r & 31) << 2;

    const float4 v0 = *((const float4*)g_acc0 + i);
    const float4 v1 = *((const float4*)g_acc1 + i);
    const float* bias = (t < T_) ? (Wk_b + t * C_) : pb1;
    float s[4];
    s[0] = v0.x + v1.x + __ldg(bias + c + 0);
    s[1] = v0.y + v1.y + __ldg(bias + c + 1);
    s[2] = v0.z + v1.z + __ldg(bias + c + 2);
    s[3] = v0.w + v1.w + __ldg(bias + c + 3);

    if (t < T_) {
        __nv_bfloat162 h0, h1, l0, l1;
        h0.x = __float2bfloat16(s[0]);
        l0.x = __float2bfloat16(s[0] - __bfloat162float(h0.x));
        h0.y = __float2bfloat16(s[1]);
        l0.y = __float2bfloat16(s[1] - __bfloat162float(h0.y));
        h1.x = __float2bfloat16(s[2]);
        l1.x = __float2bfloat16(s[2] - __bfloat162float(h1.x));
        h1.y = __float2bfloat16(s[3]);
        l1.y = __float2bfloat16(s[3] - __bfloat162float(h1.y));
        size_t off = (size_t)t * B_ * C_ + (size_t)r * 4;
        *(__nv_bfloat162*)(g_Phi + off)     = h0;
        *(__nv_bfloat162*)(g_Phi + off + 2) = h1;
        *(__nv_bfloat162*)(g_Plo + off)     = l0;
        *(__nv_bfloat162*)(g_Plo + off + 2) = l1;
    } else {
        float4 o; o.x = s[0]; o.y = s[1]; o.z = s[2]; o.w = s[3];
        *((float4*)g_h + r) = o;
    }
}

// ---------------- flash NCE via mma.sync: block = 128 q-rows x t -----------
#define FST 272                     // 128 bf16 + 16B pad
#define FTILE_ (128 * FST)          // 34816
#define FL_REDM (6 * FTILE_)
#define FL_REDL (FL_REDM + 1024)
#define FL_DIAG (FL_REDL + 1024)
#define FL_SMEM (FL_DIAG + 512)     // 211456 bytes

__global__ __launch_bounds__(256, 1) void flash_mma_kernel()
{
    extern __shared__ __align__(128) char smem[];
    const uint32_t sb = smem_u32(smem);
    float* red_m = (float*)(smem + FL_REDM);
    float* red_l = (float*)(smem + FL_REDL);
    float* diag  = (float*)(smem + FL_DIAG);

    const int rb = blockIdx.x, t = blockIdx.y;
    const int tid = threadIdx.x, lane = tid & 31, wid = tid >> 5;
    const int wm = wid >> 1, wn = wid & 1;      // warp tile 32 x 64

    const __nv_bfloat16* Ehi = g_Ehi + ((size_t)t * B_ + rb * 128) * C_;
    const __nv_bfloat16* Elo = g_Elo + ((size_t)t * B_ + rb * 128) * C_;
    const __nv_bfloat16* Phi = g_Phi + (size_t)t * B_ * C_;
    const __nv_bfloat16* Plo = g_Plo + (size_t)t * B_ * C_;

#pragma unroll
    for (int f = 0; f < 8; f++) {
        int id = tid + f * 256, r = id >> 4, ch = (id & 15) << 4;
        cp16(sb + r * FST + ch,          (const char*)Ehi + r * 256 + ch);
        cp16(sb + FTILE_ + r * FST + ch, (const char*)Elo + r * 256 + ch);
    }
    CP_COMMIT();
#pragma unroll
    for (int f = 0; f < 8; f++) {
        int id = tid + f * 256, r = id >> 4, ch = (id & 15) << 4;
        cp16(sb + 2 * FTILE_ + r * FST + ch, (const char*)Phi + r * 256 + ch);
        cp16(sb + 3 * FTILE_ + r * FST + ch, (const char*)Plo + r * 256 + ch);
    }
    CP_COMMIT();

    float m_r[4], l_r[4];
#pragma unroll
    for (int r = 0; r < 4; r++) { m_r[r] = -3.0e38f; l_r[r] = 0.0f; }

    const int a_rr = wm * 32 + (lane & 15);
    const int a_kb = (lane >> 4) << 4;
    const int b_rr = wn * 64 + (lane & 7) + ((lane >> 4) << 3);
    const int b_kb = ((lane >> 3) & 1) << 4;
    const int row4 = lane >> 2;

    for (int kt = 0; kt < 16; kt++) {
        if (kt + 1 < 16) {
            uint32_t kb = sb + (2 + ((kt + 1) & 1) * 2) * FTILE_;
            const char* sh = (const char*)Phi + (size_t)(kt + 1) * 128 * 256;
            const char* sl = (const char*)Plo + (size_t)(kt + 1) * 128 * 256;
#pragma unroll
            for (int f = 0; f < 8; f++) {
                int id = tid + f * 256, r = id >> 4, ch = (id & 15) << 4;
                cp16(kb + r * FST + ch,          sh + r * 256 + ch);
                cp16(kb + FTILE_ + r * FST + ch, sl + r * 256 + ch);
            }
            CP_COMMIT();
            CP_WAIT(1);
        } else {
            CP_WAIT(0);
        }
        __syncthreads();

        const uint32_t Qh = sb, Ql = sb + FTILE_;
        const uint32_t Kh = sb + (2 + (kt & 1) * 2) * FTILE_;
        const uint32_t Kl = Kh + FTILE_;

        float acc[2][8][4];
#pragma unroll
        for (int mi = 0; mi < 2; mi++)
#pragma unroll
            for (int ni = 0; ni < 8; ni++)
#pragma unroll
                for (int q = 0; q < 4; q++) acc[mi][ni][q] = 0.0f;

#pragma unroll
        for (int k16 = 0; k16 < 8; k16++) {
            uint32_t bh[16], bl[16];
#pragma unroll
            for (int g = 0; g < 4; g++) {
                ldmx4(bh + g * 4, Kh + (b_rr + g * 16) * FST + k16 * 32 + b_kb);
                ldmx4(bl + g * 4, Kl + (b_rr + g * 16) * FST + k16 * 32 + b_kb);
            }
#pragma unroll
            for (int mi = 0; mi < 2; mi++) {
                uint32_t a[4];
                ldmx4(a, Qh + (a_rr + mi * 16) * FST + k16 * 32 + a_kb);
#pragma unroll
                for (int ni = 0; ni < 8; ni++) mma_bf16(acc[mi][ni], a, bh + ni * 2);
#pragma unroll
                for (int ni = 0; ni < 8; ni++) mma_bf16(acc[mi][ni], a, bl + ni * 2);
            }
#pragma unroll
            for (int mi = 0; mi < 2; mi++) {
                uint32_t a[4];
                ldmx4(a, Ql + (a_rr + mi * 16) * FST + k16 * 32 + a_kb);
#pragma unroll
                for (int ni = 0; ni < 8; ni++) mma_bf16(acc[mi][ni], a, bh + ni * 2);
            }
        }

        float rmax[4];
#pragma unroll
        for (int mi = 0; mi < 2; mi++)
#pragma unroll
            for (int h = 0; h < 2; h++) {
                float m = acc[mi][0][h * 2];
#pragma unroll
                for (int ni = 0; ni < 8; ni++) {
                    m = fmaxf(m, acc[mi][ni][h * 2]);
                    m = fmaxf(m, acc[mi][ni][h * 2 + 1]);
                }
                rmax[mi * 2 + h] = m;
            }
#pragma unroll
        for (int r = 0; r < 4; r++) {
            rmax[r] = fmaxf(rmax[r], __shfl_xor_sync(0xffffffffu, rmax[r], 1));
            rmax[r] = fmaxf(rmax[r], __shfl_xor_sync(0xffffffffu, rmax[r], 2));
        }
        if ((lane & 3) == 0) {
#pragma unroll
            for (int r = 0; r < 4; r++) {
                int rg = wm * 32 + (r >> 1) * 16 + row4 + (r & 1) * 8;
                red_m[rg * 2 + wn] = rmax[r];
            }
        }
        __syncthreads();

        float m_new[4], s_r[4];
#pragma unroll
        for (int r = 0; r < 4; r++) {
            int rg = wm * 32 + (r >> 1) * 16 + row4 + (r & 1) * 8;
            float tm = fmaxf(red_m[rg * 2], red_m[rg * 2 + 1]);
            m_new[r] = fmaxf(m_r[r], tm);
        }
#pragma unroll
        for (int mi = 0; mi < 2; mi++)
#pragma unroll
            for (int h = 0; h < 2; h++) {
                float mn = m_new[mi * 2 + h];
                float s = 0.0f;
#pragma unroll
                for (int ni = 0; ni < 8; ni++) {
                    s += __expf(acc[mi][ni][h * 2] - mn);
                    s += __expf(acc[mi][ni][h * 2 + 1] - mn);
                }
                s_r[mi * 2 + h] = s;
            }
#pragma unroll
        for (int r = 0; r < 4; r++) {
            s_r[r] += __shfl_xor_sync(0xffffffffu, s_r[r], 1);
            s_r[r] += __shfl_xor_sync(0xffffffffu, s_r[r], 2);
        }
        if ((lane & 3) == 0) {
#pragma unroll
            for (int r = 0; r < 4; r++) {
                int rg = wm * 32 + (r >> 1) * 16 + row4 + (r & 1) * 8;
                red_l[rg * 2 + wn] = s_r[r];
            }
        }
        if (kt == rb) {
#pragma unroll
            for (int mi = 0; mi < 2; mi++)
#pragma unroll
                for (int ni = 0; ni < 8; ni++)
#pragma unroll
                    for (int q = 0; q < 4; q++) {
                        int rl = wm * 32 + mi * 16 + row4 + (q >> 1) * 8;
                        int cl = wn * 64 + ni * 8 + (lane & 3) * 2 + (q & 1);
                        if (rl == cl) diag[rl] = acc[mi][ni][q];
                    }
        }
        __syncthreads();
#pragma unroll
        for (int r = 0; r < 4; r++) {
            int rg = wm * 32 + (r >> 1) * 16 + row4 + (r & 1) * 8;
            float ts = red_l[rg * 2] + red_l[rg * 2 + 1];
            l_r[r] = l_r[r] * __expf(m_r[r] - m_new[r]) + ts;
            m_r[r] = m_new[r];
        }
    }

    if (wn == 0 && (lane & 3) == 0) {
        float v = 0.0f;
#pragma unroll
        for (int r = 0; r < 4; r++) {
            int rg = wm * 32 + (r >> 1) * 16 + row4 + (r & 1) * 8;
            v += diag[rg] - (m_r[r] + logf(l_r[r]));
        }
        atomicAdd(&g_nce, v);
    }
}

// ---------------- BatchNorm statistics -------------------------------------
__global__ void bnstat_kernel()
{
    const int c   = blockIdx.x;
    const int tid = threadIdx.x;
    float s = 0.0f, sq = 0.0f;
    for (int b = tid; b < B_; b += 256) {
        float v = g_h[(size_t)b * C_ + c];
        s += v;
        sq = fmaf(v, v, sq);
    }
    __shared__ float ss[256], sqq[256];
    ss[tid] = s; sqq[tid] = sq;
    __syncthreads();
    for (int st = 128; st > 0; st >>= 1) {
        if (tid < st) { ss[tid] += ss[tid + st]; sqq[tid] += sqq[tid + st]; }
        __syncthreads();
    }
    if (tid == 0) {
        float mean = ss[0] * (1.0f / B_);
        float var  = sqq[0] * (1.0f / B_) - mean * mean;
        g_mean[c] = mean;
        g_rstd[c] = rsqrtf(var + 1e-5f);
    }
}

// ---------------- projection head ------------------------------------------
__global__ void proj_kernel(const float* __restrict__ gamma,
                            const float* __restrict__ beta,
                            const float* __restrict__ pw2,
                            const float* __restrict__ pb2,
                            float* __restrict__ out)
{
    __shared__ float w2s[P_][132];
    __shared__ float hn[32][129];
    __shared__ float mg[C_], bg[C_];

    const int tid  = threadIdx.x;
    const int base = blockIdx.x * 32;

    for (int f = tid; f < P_ * C_; f += 256) {
        int p = f >> 7, c = f & 127;
        w2s[p][c] = pw2[f];
    }
    if (tid < C_) {
        float sc = g_rstd[tid] * gamma[tid];
        mg[tid] = sc;
        bg[tid] = beta[tid] - g_mean[tid] * sc;
    }
    __syncthreads();

    for (int f = tid; f < 32 * C_; f += 256) {
        int r = f >> 7, c = f & 127;
        float v = g_h[(size_t)(base + r) * C_ + c];
        v = v * mg[c] + bg[c];
        v = (v >= 0.0f) ? v : 0.01f * v;
        hn[r][c] = v;
    }
    __syncthreads();

    const int r  = tid >> 3;
    const int pg = (tid & 7) * 4;
    float accp[4];
#pragma unroll
    for (int p = 0; p < 4; p++) accp[p] = 0.0f;
    for (int c = 0; c < C_; c++) {
        float hv = hn[r][c];
#pragma unroll
        for (int p = 0; p < 4; p++)
            accp[p] = fmaf(hv, w2s[pg + p][c], accp[p]);
    }
#pragma unroll
    for (int p = 0; p < 4; p++)
        out[1 + (size_t)(base + r) * P_ + pg + p] = accp[p] + pb2[pg + p];

    if (blockIdx.x == 0 && tid == 0)
        out[0] = g_nce * (-1.0f / (float)(B_ * T_));
}

// ---------------- launch ---------------------------------------------------
extern "C" void kernel_launch(void* const* d_in, const int* in_sizes, int n_in,
                              void* d_out, int out_size)
{
    const float* z     = (const float*)d_in[0];
    const float* c_t   = (const float*)d_in[1];
    const float* Wk_w  = (const float*)d_in[2];
    const float* Wk_b  = (const float*)d_in[3];
    const float* pw1   = (const float*)d_in[4];
    const float* pb1   = (const float*)d_in[5];
    const float* gamma = (const float*)d_in[6];
    const float* beta  = (const float*)d_in[7];
    const float* pw2   = (const float*)d_in[8];
    const float* pb2   = (const float*)d_in[9];
    float* out = (float*)d_out;

    init_kernel<<<(B_ * C_ + 255) / 256, 256>>>(z);
    convA_kernel<<<4096, 256>>>(c_t);
    convW_kernel<<<4864, 256>>>(Wk_w, pw1);

    gemm_mma_kernel<<<NPCTAS, 256>>>();

    combine_kernel<<<NT * B_ * C_ / 4 / 256, 256>>>(Wk_b, pb1);

    cudaFuncSetAttribute(flash_mma_kernel,
                         cudaFuncAttributeMaxDynamicSharedMemorySize, FL_SMEM);
    flash_mma_kernel<<<dim3(B_ / 128, T_), 256, FL_SMEM>>>();

    bnstat_kernel<<<C_, 256>>>();
    proj_kernel<<<B_ / 32, 256>>>(gamma, beta, pw2, pb2, out);
}

// round 14
// speedup vs baseline: 1.1429x; 1.1429x over previous
#include <cuda_runtime.h>
#include <cuda_bf16.h>
#include <cstdint>

#define B_ 2048
#define T_ 18
#define C_ 128
#define D_ 4096
#define P_ 32
#define NT 19               // 18 timesteps + pw1 block
#define NUNITS 1216         // 19 t * 16 rt * 2 nh * 2 kh
#define NPCTAS 296

// ---------------- scratch (device globals; no allocation allowed) ----------
__device__ float g_h   [B_ * C_];
__device__ float g_mean[C_];
__device__ float g_rstd[C_];
__device__ float g_nce;
__device__ int   g_work;

// fp32 partial accumulators for the K-split GEMM: [t][b][c]
__device__ __align__(16) float g_acc0[NT * B_ * C_];
__device__ __align__(16) float g_acc1[NT * B_ * C_];

// mma-fragment-packed operands.
__device__ __align__(16) uint4 g_Afh[16 * 256 * 8 * 32];
__device__ __align__(16) uint4 g_Afl[16 * 256 * 8 * 32];
__device__ __align__(16) uint4 g_Wfh[NT * 256 * 8 * 32];
__device__ __align__(16) uint4 g_Wfl[NT * 256 * 8 * 32];

// bf16 hi/lo enc + pred for flash: [t][b][c] row-major (C=128)
__device__ __align__(16) __nv_bfloat16 g_Ehi[T_ * B_ * C_];
__device__ __align__(16) __nv_bfloat16 g_Elo[T_ * B_ * C_];
__device__ __align__(16) __nv_bfloat16 g_Phi[T_ * B_ * C_];
__device__ __align__(16) __nv_bfloat16 g_Plo[T_ * B_ * C_];

// ---------------- helpers ---------------------------------------------------
__device__ __forceinline__ uint32_t smem_u32(const void* p) {
    uint32_t a;
    asm("{ .reg .u64 t; cvta.to.shared.u64 t, %1; cvt.u32.u64 %0, t; }"
        : "=r"(a) : "l"(p));
    return a;
}

__device__ __forceinline__ void cp16(uint32_t dst, const void* src) {
    asm volatile("cp.async.cg.shared.global [%0], [%1], 16;"
                 :: "r"(dst), "l"(src) : "memory");
}
#define CP_COMMIT() asm volatile("cp.async.commit_group;" ::: "memory")
#define CP_WAIT(N)  asm volatile("cp.async.wait_group %0;" :: "n"(N) : "memory")

__device__ __forceinline__ void ldmx4(uint32_t* r, uint32_t addr) {
    asm volatile("ldmatrix.sync.aligned.m8n8.x4.shared.b16 {%0,%1,%2,%3}, [%4];"
                 : "=r"(r[0]), "=r"(r[1]), "=r"(r[2]), "=r"(r[3]) : "r"(addr));
}

__device__ __forceinline__ void mma_bf16(float* c, const uint32_t* a,
                                         const uint32_t* b) {
    asm volatile(
        "mma.sync.aligned.m16n8k16.row.col.f32.bf16.bf16.f32 "
        "{%0,%1,%2,%3}, {%4,%5,%6,%7}, {%8,%9}, {%0,%1,%2,%3};"
        : "+f"(c[0]), "+f"(c[1]), "+f"(c[2]), "+f"(c[3])
        : "r"(a[0]), "r"(a[1]), "r"(a[2]), "r"(a[3]), "r"(b[0]), "r"(b[1]));
}

__device__ __forceinline__ uint32_t pack_bf16(float x, float y) {
    __nv_bfloat162 v;
    v.x = __float2bfloat16(x);
    v.y = __float2bfloat16(y);
    return *(uint32_t*)&v;
}
__device__ __forceinline__ void hilo_pack(float x, float y,
                                          uint32_t& h, uint32_t& l) {
    __nv_bfloat16 hx = __float2bfloat16(x);
    __nv_bfloat16 hy = __float2bfloat16(y);
    h = pack_bf16(x, y);
    l = pack_bf16(x - __bfloat162float(hx), y - __bfloat162float(hy));
}

// ---------------- init: z_aug2 [B,C,T] -> Ehi/Elo [T,B,C]; zero nce/work ---
__global__ void init_kernel(const float* __restrict__ z)
{
    int bc = blockIdx.x * blockDim.x + threadIdx.x;
    if (bc == 0) { g_nce = 0.0f; g_work = 0; }
    if (bc < B_ * C_) {
        const float* src = z + (size_t)bc * T_;
#pragma unroll
        for (int t = 0; t < T_; t++) {
            float v = src[t];
            __nv_bfloat16 hi = __float2bfloat16(v);
            __nv_bfloat16 lo = __float2bfloat16(v - __bfloat162float(hi));
            g_Ehi[(size_t)t * B_ * C_ + bc] = hi;
            g_Elo[(size_t)t * B_ * C_ + bc] = lo;
        }
    }
}

// ---------------- pack A (c_t) into mma A-fragment layout -------------------
__global__ void convA_kernel(const float* __restrict__ A)
{
    int id = blockIdx.x * 256 + threadIdx.x;      // 0 .. 1048575
    int lane = id & 31;
    int b = id >> 5;                               // 0 .. 32767
    int mi = b & 7, kg = (b >> 3) & 255, rt = b >> 11;
    int row = rt * 128 + mi * 16 + (lane >> 2);
    int k   = kg * 16 + (lane & 3) * 2;

    const float* r0 = A + (size_t)row * D_ + k;
    const float* r1 = r0 + 8 * D_;
    uint4 h, l;
    hilo_pack(r0[0], r0[1], h.x, l.x);
    hilo_pack(r1[0], r1[1], h.y, l.y);
    hilo_pack(r0[8], r0[9], h.z, l.z);
    hilo_pack(r1[8], r1[9], h.w, l.w);
    g_Afh[(size_t)b * 32 + lane] = h;
    g_Afl[(size_t)b * 32 + lane] = l;
}

// ---------------- pack W (Wk_w + pw1) into mma B-fragment layout ------------
__global__ void convW_kernel(const float* __restrict__ Wk_w,
                             const float* __restrict__ pw1)
{
    int id = blockIdx.x * 256 + threadIdx.x;      // 0 .. 1245183
    int lane = id & 31;
    int b = id >> 5;                               // 0 .. 38911
    int g = b & 7, kg = (b >> 3) & 255, t = b >> 11;
    int n0 = g * 16 + (lane >> 2);
    int k  = kg * 16 + (lane & 3) * 2;

    const float* s0 = (t < T_) ? (Wk_w + ((size_t)t * C_ + n0) * D_ + k)
                               : (pw1 + (size_t)n0 * D_ + k);
    const float* s1 = s0 + 8 * D_;
    uint4 h, l;
    hilo_pack(s0[0], s0[1], h.x, l.x);
    hilo_pack(s0[8], s0[9], h.y, l.y);
    hilo_pack(s1[0], s1[1], h.z, l.z);
    hilo_pack(s1[8], s1[9], h.w, l.w);
    g_Wfh[(size_t)b * 32 + lane] = h;
    g_Wfl[(size_t)b * 32 + lane] = l;
}

// ---------------- persistent mma.sync GEMM, fragments direct from L2 -------
// (round-10 version: single timestep per unit, NUNITS=1216)
__global__ __launch_bounds__(256, 2) void gemm_mma_kernel()
{
    __shared__ int s_u;
    const int tid = threadIdx.x;
    const int lane = tid & 31, wid = tid >> 5;
    const int wm = wid >> 1, wn = wid & 1;     // warp tile 32x32

    for (;;) {
        __syncthreads();
        if (tid == 0) s_u = atomicAdd(&g_work, 1);
        __syncthreads();
        const int u = s_u;
        if (u >= NUNITS) break;

        const int tb = u >> 6;
        const int r6 = u & 63;
        const int kh = r6 & 1;
        const int nh = (r6 >> 1) & 1;
        const int rt = r6 >> 2;

        float acc[2][4][4];
#pragma unroll
        for (int mi = 0; mi < 2; mi++)
#pragma unroll
            for (int ni = 0; ni < 4; ni++)
#pragma unroll
                for (int q = 0; q < 4; q++) acc[mi][ni][q] = 0.0f;

        const uint4* pAh = g_Afh +
            ((size_t)(rt * 256 + kh * 128) * 8 + 2 * wm) * 32 + lane;
        const uint4* pAl = g_Afl +
            ((size_t)(rt * 256 + kh * 128) * 8 + 2 * wm) * 32 + lane;
        const uint4* pWh = g_Wfh +
            ((size_t)(tb * 256 + kh * 128) * 8 + nh * 4 + wn * 2) * 32 + lane;
        const uint4* pWl = g_Wfl +
            ((size_t)(tb * 256 + kh * 128) * 8 + nh * 4 + wn * 2) * 32 + lane;

#pragma unroll 2
        for (int kg = 0; kg < 128; kg++) {
            uint32_t ah[8], al[8], wh[8], wl[8];
            {
                uint4 v;
                v = pAh[0];  ah[0] = v.x; ah[1] = v.y; ah[2] = v.z; ah[3] = v.w;
                v = pAh[32]; ah[4] = v.x; ah[5] = v.y; ah[6] = v.z; ah[7] = v.w;
                v = pAl[0];  al[0] = v.x; al[1] = v.y; al[2] = v.z; al[3] = v.w;
                v = pAl[32]; al[4] = v.x; al[5] = v.y; al[6] = v.z; al[7] = v.w;
                v = pWh[0];  wh[0] = v.x; wh[1] = v.y; wh[2] = v.z; wh[3] = v.w;
                v = pWh[32]; wh[4] = v.x; wh[5] = v.y; wh[6] = v.z; wh[7] = v.w;
                v = pWl[0];  wl[0] = v.x; wl[1] = v.y; wl[2] = v.z; wl[3] = v.w;
                v = pWl[32]; wl[4] = v.x; wl[5] = v.y; wl[6] = v.z; wl[7] = v.w;
            }
            pAh += 256; pAl += 256; pWh += 256; pWl += 256;

#pragma unroll
            for (int mi = 0; mi < 2; mi++) {
#pragma unroll
                for (int ni = 0; ni < 4; ni++)
                    mma_bf16(acc[mi][ni], ah + mi * 4, wh + ni * 2);
#pragma unroll
                for (int ni = 0; ni < 4; ni++)
                    mma_bf16(acc[mi][ni], ah + mi * 4, wl + ni * 2);
            }
#pragma unroll
            for (int mi = 0; mi < 2; mi++)
#pragma unroll
                for (int ni = 0; ni < 4; ni++)
                    mma_bf16(acc[mi][ni], al + mi * 4, wh + ni * 2);
        }

        float* outp = (kh ? g_acc1 : g_acc0) + (size_t)tb * B_ * C_;
        const int r0 = rt * 128 + wm * 32 + (lane >> 2);
        const int c0 = nh * 64 + wn * 32 + (lane & 3) * 2;
#pragma unroll
        for (int mi = 0; mi < 2; mi++)
#pragma unroll
            for (int ni = 0; ni < 4; ni++) {
                int row = r0 + mi * 16, col = c0 + ni * 8;
                float2 v;
                v.x = acc[mi][ni][0]; v.y = acc[mi][ni][1];
                *(float2*)(outp + (size_t)row * C_ + col) = v;
                v.x = acc[mi][ni][2]; v.y = acc[mi][ni][3];
                *(float2*)(outp + (size_t)(row + 8) * C_ + col) = v;
            }
    }
}

// ---------------- combine: acc0+acc1+bias -> Phi/Plo (t<18) or g_h ---------
__global__ void combine_kernel(const float* __restrict__ Wk_b,
                               const float* __restrict__ pb1)
{
    const int per_t = B_ * C_ / 4;
    int i = blockIdx.x * 256 + threadIdx.x;
    int t = i / per_t;
    int r = i - t * per_t;
    int c = (r & 31) << 2;

    const float4 v0 = *((const float4*)g_acc0 + i);
    const float4 v1 = *((const float4*)g_acc1 + i);
    const float* bias = (t < T_) ? (Wk_b + t * C_) : pb1;
    float s[4];
    s[0] = v0.x + v1.x + __ldg(bias + c + 0);
    s[1] = v0.y + v1.y + __ldg(bias + c + 1);
    s[2] = v0.z + v1.z + __ldg(bias + c + 2);
    s[3] = v0.w + v1.w + __ldg(bias + c + 3);

    if (t < T_) {
        __nv_bfloat162 h0, h1, l0, l1;
        h0.x = __float2bfloat16(s[0]);
        l0.x = __float2bfloat16(s[0] - __bfloat162float(h0.x));
        h0.y = __float2bfloat16(s[1]);
        l0.y = __float2bfloat16(s[1] - __bfloat162float(h0.y));
        h1.x = __float2bfloat16(s[2]);
        l1.x = __float2bfloat16(s[2] - __bfloat162float(h1.x));
        h1.y = __float2bfloat16(s[3]);
        l1.y = __float2bfloat16(s[3] - __bfloat162float(h1.y));
        size_t off = (size_t)t * B_ * C_ + (size_t)r * 4;
        *(__nv_bfloat162*)(g_Phi + off)     = h0;
        *(__nv_bfloat162*)(g_Phi + off + 2) = h1;
        *(__nv_bfloat162*)(g_Plo + off)     = l0;
        *(__nv_bfloat162*)(g_Plo + off + 2) = l1;
    } else {
        float4 o; o.x = s[0]; o.y = s[1]; o.z = s[2]; o.w = s[3];
        *((float4*)g_h + r) = o;
    }
}

// ---------------- flash NCE via mma.sync: 512 threads, warp tile 16x64 -----
#define FST 272                     // 128 bf16 + 16B pad
#define FTILE_ (128 * FST)          // 34816
#define FL_REDM (6 * FTILE_)
#define FL_REDL (FL_REDM + 1024)
#define FL_DIAG (FL_REDL + 1024)
#define FL_SMEM (FL_DIAG + 512)     // 211456 bytes

__global__ __launch_bounds__(512, 1) void flash_mma_kernel()
{
    extern __shared__ __align__(128) char smem[];
    const uint32_t sb = smem_u32(smem);
    float* red_m = (float*)(smem + FL_REDM);
    float* red_l = (float*)(smem + FL_REDL);
    float* diag  = (float*)(smem + FL_DIAG);

    const int rb = blockIdx.x, t = blockIdx.y;
    const int tid = threadIdx.x, lane = tid & 31, wid = tid >> 5;
    const int wm = wid >> 1, wn = wid & 1;      // warp tile 16 x 64, wm 0..7

    const __nv_bfloat16* Ehi = g_Ehi + ((size_t)t * B_ + rb * 128) * C_;
    const __nv_bfloat16* Elo = g_Elo + ((size_t)t * B_ + rb * 128) * C_;
    const __nv_bfloat16* Phi = g_Phi + (size_t)t * B_ * C_;
    const __nv_bfloat16* Plo = g_Plo + (size_t)t * B_ * C_;

#pragma unroll
    for (int f = 0; f < 4; f++) {
        int id = tid + f * 512, r = id >> 4, ch = (id & 15) << 4;
        cp16(sb + r * FST + ch,          (const char*)Ehi + r * 256 + ch);
        cp16(sb + FTILE_ + r * FST + ch, (const char*)Elo + r * 256 + ch);
    }
    CP_COMMIT();
#pragma unroll
    for (int f = 0; f < 4; f++) {
        int id = tid + f * 512, r = id >> 4, ch = (id & 15) << 4;
        cp16(sb + 2 * FTILE_ + r * FST + ch, (const char*)Phi + r * 256 + ch);
        cp16(sb + 3 * FTILE_ + r * FST + ch, (const char*)Plo + r * 256 + ch);
    }
    CP_COMMIT();

    // per-thread online-softmax state: 2 rows (row4 and row4+8 within m16)
    float m_r[2], l_r[2];
#pragma unroll
    for (int r = 0; r < 2; r++) { m_r[r] = -3.0e38f; l_r[r] = 0.0f; }

    const int a_rr = wm * 16 + (lane & 15);
    const int a_kb = (lane >> 4) << 4;
    const int b_rr = wn * 64 + (lane & 7) + ((lane >> 4) << 3);
    const int b_kb = ((lane >> 3) & 1) << 4;
    const int row4 = lane >> 2;

    for (int kt = 0; kt < 16; kt++) {
        if (kt + 1 < 16) {
            uint32_t kb = sb + (2 + ((kt + 1) & 1) * 2) * FTILE_;
            const char* sh = (const char*)Phi + (size_t)(kt + 1) * 128 * 256;
            const char* sl = (const char*)Plo + (size_t)(kt + 1) * 128 * 256;
#pragma unroll
            for (int f = 0; f < 4; f++) {
                int id = tid + f * 512, r = id >> 4, ch = (id & 15) << 4;
                cp16(kb + r * FST + ch,          sh + r * 256 + ch);
                cp16(kb + FTILE_ + r * FST + ch, sl + r * 256 + ch);
            }
            CP_COMMIT();
            CP_WAIT(1);
        } else {
            CP_WAIT(0);
        }
        __syncthreads();

        const uint32_t Qh = sb, Ql = sb + FTILE_;
        const uint32_t Kh = sb + (2 + (kt & 1) * 2) * FTILE_;
        const uint32_t Kl = Kh + FTILE_;

        float acc[8][4];
#pragma unroll
        for (int ni = 0; ni < 8; ni++)
#pragma unroll
            for (int q = 0; q < 4; q++) acc[ni][q] = 0.0f;

#pragma unroll
        for (int k16 = 0; k16 < 8; k16++) {
            uint32_t bh[16], bl[16];
#pragma unroll
            for (int g = 0; g < 4; g++) {
                ldmx4(bh + g * 4, Kh + (b_rr + g * 16) * FST + k16 * 32 + b_kb);
                ldmx4(bl + g * 4, Kl + (b_rr + g * 16) * FST + k16 * 32 + b_kb);
            }
            {
                uint32_t a[4];
                ldmx4(a, Qh + a_rr * FST + k16 * 32 + a_kb);
#pragma unroll
                for (int ni = 0; ni < 8; ni++) mma_bf16(acc[ni], a, bh + ni * 2);
#pragma unroll
                for (int ni = 0; ni < 8; ni++) mma_bf16(acc[ni], a, bl + ni * 2);
            }
            {
                uint32_t a[4];
                ldmx4(a, Ql + a_rr * FST + k16 * 32 + a_kb);
#pragma unroll
                for (int ni = 0; ni < 8; ni++) mma_bf16(acc[ni], a, bh + ni * 2);
            }
        }

        // ---- online softmax ----
        float rmax[2];
#pragma unroll
        for (int h = 0; h < 2; h++) {
            float m = acc[0][h * 2];
#pragma unroll
            for (int ni = 0; ni < 8; ni++) {
                m = fmaxf(m, acc[ni][h * 2]);
                m = fmaxf(m, acc[ni][h * 2 + 1]);
            }
            rmax[h] = m;
        }
#pragma unroll
        for (int r = 0; r < 2; r++) {
            rmax[r] = fmaxf(rmax[r], __shfl_xor_sync(0xffffffffu, rmax[r], 1));
            rmax[r] = fmaxf(rmax[r], __shfl_xor_sync(0xffffffffu, rmax[r], 2));
        }
        if ((lane & 3) == 0) {
#pragma unroll
            for (int r = 0; r < 2; r++) {
                int rg = wm * 16 + row4 + r * 8;
                red_m[rg * 2 + wn] = rmax[r];
            }
        }
        __syncthreads();

        float m_new[2], s_r[2];
#pragma unroll
        for (int r = 0; r < 2; r++) {
            int rg = wm * 16 + row4 + r * 8;
            float tm = fmaxf(red_m[rg * 2], red_m[rg * 2 + 1]);
            m_new[r] = fmaxf(m_r[r], tm);
        }
#pragma unroll
        for (int h = 0; h < 2; h++) {
            float mn = m_new[h];
            float s = 0.0f;
#pragma unroll
            for (int ni = 0; ni < 8; ni++) {
                s += __expf(acc[ni][h * 2] - mn);
                s += __expf(acc[ni][h * 2 + 1] - mn);
            }
            s_r[h] = s;
        }
#pragma unroll
        for (int r = 0; r < 2; r++) {
            s_r[r] += __shfl_xor_sync(0xffffffffu, s_r[r], 1);
            s_r[r] += __shfl_xor_sync(0xffffffffu, s_r[r], 2);
        }
        if ((lane & 3) == 0) {
#pragma unroll
            for (int r = 0; r < 2; r++) {
                int rg = wm * 16 + row4 + r * 8;
                red_l[rg * 2 + wn] = s_r[r];
            }
        }
        if (kt == rb) {     // diagonal capture (raw logits)
#pragma unroll
            for (int ni = 0; ni < 8; ni++)
#pragma unroll
                for (int q = 0; q < 4; q++) {
                    int rl = wm * 16 + row4 + (q >> 1) * 8;
                    int cl = wn * 64 + ni * 8 + (lane & 3) * 2 + (q & 1);
                    if (rl == cl) diag[rl] = acc[ni][q];
                }
        }
        __syncthreads();
#pragma unroll
        for (int r = 0; r < 2; r++) {
            int rg = wm * 16 + row4 + r * 8;
            float ts = red_l[rg * 2] + red_l[rg * 2 + 1];
            l_r[r] = l_r[r] * __expf(m_r[r] - m_new[r]) + ts;
            m_r[r] = m_new[r];
        }
    }

    if (wn == 0 && (lane & 3) == 0) {
        float v = 0.0f;
#pragma unroll
        for (int r = 0; r < 2; r++) {
            int rg = wm * 16 + row4 + r * 8;
            v += diag[rg] - (m_r[r] + logf(l_r[r]));
        }
        atomicAdd(&g_nce, v);
    }
}

// ---------------- BatchNorm statistics -------------------------------------
__global__ void bnstat_kernel()
{
    const int c   = blockIdx.x;
    const int tid = threadIdx.x;
    float s = 0.0f, sq = 0.0f;
    for (int b = tid; b < B_; b += 256) {
        float v = g_h[(size_t)b * C_ + c];
        s += v;
        sq = fmaf(v, v, sq);
    }
    __shared__ float ss[256], sqq[256];
    ss[tid] = s; sqq[tid] = sq;
    __syncthreads();
    for (int st = 128; st > 0; st >>= 1) {
        if (tid < st) { ss[tid] += ss[tid + st]; sqq[tid] += sqq[tid + st]; }
        __syncthreads();
    }
    if (tid == 0) {
        float mean = ss[0] * (1.0f / B_);
        float var  = sqq[0] * (1.0f / B_) - mean * mean;
        g_mean[c] = mean;
        g_rstd[c] = rsqrtf(var + 1e-5f);
    }
}

// ---------------- projection head ------------------------------------------
__global__ void proj_kernel(const float* __restrict__ gamma,
                            const float* __restrict__ beta,
                            const float* __restrict__ pw2,
                            const float* __restrict__ pb2,
                            float* __restrict__ out)
{
    __shared__ float w2s[P_][132];
    __shared__ float hn[32][129];
    __shared__ float mg[C_], bg[C_];

    const int tid  = threadIdx.x;
    const int base = blockIdx.x * 32;

    for (int f = tid; f < P_ * C_; f += 256) {
        int p = f >> 7, c = f & 127;
        w2s[p][c] = pw2[f];
    }
    if (tid < C_) {
        float sc = g_rstd[tid] * gamma[tid];
        mg[tid] = sc;
        bg[tid] = beta[tid] - g_mean[tid] * sc;
    }
    __syncthreads();

    for (int f = tid; f < 32 * C_; f += 256) {
        int r = f >> 7, c = f & 127;
        float v = g_h[(size_t)(base + r) * C_ + c];
        v = v * mg[c] + bg[c];
        v = (v >= 0.0f) ? v : 0.01f * v;
        hn[r][c] = v;
    }
    __syncthreads();

    const int r  = tid >> 3;
    const int pg = (tid & 7) * 4;
    float accp[4];
#pragma unroll
    for (int p = 0; p < 4; p++) accp[p] = 0.0f;
    for (int c = 0; c < C_; c++) {
        float hv = hn[r][c];
#pragma unroll
        for (int p = 0; p < 4; p++)
            accp[p] = fmaf(hv, w2s[pg + p][c], accp[p]);
    }
#pragma unroll
    for (int p = 0; p < 4; p++)
        out[1 + (size_t)(base + r) * P_ + pg + p] = accp[p] + pb2[pg + p];

    if (blockIdx.x == 0 && tid == 0)
        out[0] = g_nce * (-1.0f / (float)(B_ * T_));
}

// ---------------- launch ---------------------------------------------------
extern "C" void kernel_launch(void* const* d_in, const int* in_sizes, int n_in,
                              void* d_out, int out_size)
{
    const float* z     = (const float*)d_in[0];
    const float* c_t   = (const float*)d_in[1];
    const float* Wk_w  = (const float*)d_in[2];
    const float* Wk_b  = (const float*)d_in[3];
    const float* pw1   = (const float*)d_in[4];
    const float* pb1   = (const float*)d_in[5];
    const float* gamma = (const float*)d_in[6];
    const float* beta  = (const float*)d_in[7];
    const float* pw2   = (const float*)d_in[8];
    const float* pb2   = (const float*)d_in[9];
    float* out = (float*)d_out;

    init_kernel<<<(B_ * C_ + 255) / 256, 256>>>(z);
    convA_kernel<<<4096, 256>>>(c_t);
    convW_kernel<<<4864, 256>>>(Wk_w, pw1);

    gemm_mma_kernel<<<NPCTAS, 256>>>();

    combine_kernel<<<NT * B_ * C_ / 4 / 256, 256>>>(Wk_b, pb1);

    cudaFuncSetAttribute(flash_mma_kernel,
                         cudaFuncAttributeMaxDynamicSharedMemorySize, FL_SMEM);
    flash_mma_kernel<<<dim3(B_ / 128, T_), 512, FL_SMEM>>>();

    bnstat_kernel<<<C_, 256>>>();
    proj_kernel<<<B_ / 32, 256>>>(gamma, beta, pw2, pb2, out);
}

// round 17
// speedup vs baseline: 1.1907x; 1.0418x over previous
#include <cuda_runtime.h>
#include <cuda_bf16.h>
#include <cstdint>

#define B_ 2048
#define T_ 18
#define C_ 128
#define D_ 4096
#define P_ 32
#define NT 19               // 18 timesteps + pw1 block
#define NUNITS 1216         // 19 t * 16 rt * 2 nh * 2 kh
#define NPCTAS 296

// ---------------- scratch (device globals; no allocation allowed) ----------
__device__ float g_h   [B_ * C_];
__device__ float g_mean[C_];
__device__ float g_rstd[C_];
__device__ float g_nce;
__device__ int   g_work;

// fp32 partial accumulators for the K-split GEMM: [t][b][c]
__device__ __align__(16) float g_acc0[NT * B_ * C_];
__device__ __align__(16) float g_acc1[NT * B_ * C_];

// mma-fragment-packed operands.
__device__ __align__(16) uint4 g_Afh[16 * 256 * 8 * 32];
__device__ __align__(16) uint4 g_Afl[16 * 256 * 8 * 32];
__device__ __align__(16) uint4 g_Wfh[NT * 256 * 8 * 32];
__device__ __align__(16) uint4 g_Wfl[NT * 256 * 8 * 32];

// bf16 hi/lo enc + pred for flash: [t][b][c] row-major (C=128)
__device__ __align__(16) __nv_bfloat16 g_Ehi[T_ * B_ * C_];
__device__ __align__(16) __nv_bfloat16 g_Elo[T_ * B_ * C_];
__device__ __align__(16) __nv_bfloat16 g_Phi[T_ * B_ * C_];
__device__ __align__(16) __nv_bfloat16 g_Plo[T_ * B_ * C_];

// ---------------- helpers ---------------------------------------------------
__device__ __forceinline__ uint32_t smem_u32(const void* p) {
    uint32_t a;
    asm("{ .reg .u64 t; cvta.to.shared.u64 t, %1; cvt.u32.u64 %0, t; }"
        : "=r"(a) : "l"(p));
    return a;
}

__device__ __forceinline__ void cp16(uint32_t dst, const void* src) {
    asm volatile("cp.async.cg.shared.global [%0], [%1], 16;"
                 :: "r"(dst), "l"(src) : "memory");
}
#define CP_COMMIT() asm volatile("cp.async.commit_group;" ::: "memory")
#define CP_WAIT(N)  asm volatile("cp.async.wait_group %0;" :: "n"(N) : "memory")

__device__ __forceinline__ void ldmx4(uint32_t* r, uint32_t addr) {
    asm volatile("ldmatrix.sync.aligned.m8n8.x4.shared.b16 {%0,%1,%2,%3}, [%4];"
                 : "=r"(r[0]), "=r"(r[1]), "=r"(r[2]), "=r"(r[3]) : "r"(addr));
}

__device__ __forceinline__ void mma_bf16(float* c, const uint32_t* a,
                                         const uint32_t* b) {
    asm volatile(
        "mma.sync.aligned.m16n8k16.row.col.f32.bf16.bf16.f32 "
        "{%0,%1,%2,%3}, {%4,%5,%6,%7}, {%8,%9}, {%0,%1,%2,%3};"
        : "+f"(c[0]), "+f"(c[1]), "+f"(c[2]), "+f"(c[3])
        : "r"(a[0]), "r"(a[1]), "r"(a[2]), "r"(a[3]), "r"(b[0]), "r"(b[1]));
}

__device__ __forceinline__ uint32_t pack_bf16(float x, float y) {
    __nv_bfloat162 v;
    v.x = __float2bfloat16(x);
    v.y = __float2bfloat16(y);
    return *(uint32_t*)&v;
}
__device__ __forceinline__ void hilo_pack(float x, float y,
                                          uint32_t& h, uint32_t& l) {
    __nv_bfloat16 hx = __float2bfloat16(x);
    __nv_bfloat16 hy = __float2bfloat16(y);
    h = pack_bf16(x, y);
    l = pack_bf16(x - __bfloat162float(hx), y - __bfloat162float(hy));
}

// ---------------- init: z_aug2 [B,C,T] -> Ehi/Elo [T,B,C]; zero nce/work ---
__global__ void init_kernel(const float* __restrict__ z)
{
    int bc = blockIdx.x * blockDim.x + threadIdx.x;
    if (bc == 0) { g_nce = 0.0f; g_work = 0; }
    if (bc < B_ * C_) {
        const float* src = z + (size_t)bc * T_;
#pragma unroll
        for (int t = 0; t < T_; t++) {
            float v = src[t];
            __nv_bfloat16 hi = __float2bfloat16(v);
            __nv_bfloat16 lo = __float2bfloat16(v - __bfloat162float(hi));
            g_Ehi[(size_t)t * B_ * C_ + bc] = hi;
            g_Elo[(size_t)t * B_ * C_ + bc] = lo;
        }
    }
}

// ---------------- pack A (c_t) into mma A-fragment layout -------------------
__global__ void convA_kernel(const float* __restrict__ A)
{
    int id = blockIdx.x * 256 + threadIdx.x;      // 0 .. 1048575
    int lane = id & 31;
    int b = id >> 5;                               // 0 .. 32767
    int mi = b & 7, kg = (b >> 3) & 255, rt = b >> 11;
    int row = rt * 128 + mi * 16 + (lane >> 2);
    int k   = kg * 16 + (lane & 3) * 2;

    const float* r0 = A + (size_t)row * D_ + k;
    const float* r1 = r0 + 8 * D_;
    uint4 h, l;
    hilo_pack(r0[0], r0[1], h.x, l.x);
    hilo_pack(r1[0], r1[1], h.y, l.y);
    hilo_pack(r0[8], r0[9], h.z, l.z);
    hilo_pack(r1[8], r1[9], h.w, l.w);
    g_Afh[(size_t)b * 32 + lane] = h;
    g_Afl[(size_t)b * 32 + lane] = l;
}

// ---------------- pack W (Wk_w + pw1) into mma B-fragment layout ------------
__global__ void convW_kernel(const float* __restrict__ Wk_w,
                             const float* __restrict__ pw1)
{
    int id = blockIdx.x * 256 + threadIdx.x;      // 0 .. 1245183
    int lane = id & 31;
    int b = id >> 5;                               // 0 .. 38911
    int g = b & 7, kg = (b >> 3) & 255, t = b >> 11;
    int n0 = g * 16 + (lane >> 2);
    int k  = kg * 16 + (lane & 3) * 2;

    const float* s0 = (t < T_) ? (Wk_w + ((size_t)t * C_ + n0) * D_ + k)
                               : (pw1 + (size_t)n0 * D_ + k);
    const float* s1 = s0 + 8 * D_;
    uint4 h, l;
    hilo_pack(s0[0], s0[1], h.x, l.x);
    hilo_pack(s0[8], s0[9], h.y, l.y);
    hilo_pack(s1[0], s1[1], h.z, l.z);
    hilo_pack(s1[8], s1[9], h.w, l.w);
    g_Wfh[(size_t)b * 32 + lane] = h;
    g_Wfl[(size_t)b * 32 + lane] = l;
}

// ---------------- persistent mma.sync GEMM, fragments direct from L2 -------
__global__ __launch_bounds__(256, 2) void gemm_mma_kernel()
{
    __shared__ int s_u;
    const int tid = threadIdx.x;
    const int lane = tid & 31, wid = tid >> 5;
    const int wm = wid >> 1, wn = wid & 1;     // warp tile 32x32

    for (;;) {
        __syncthreads();
        if (tid == 0) s_u = atomicAdd(&g_work, 1);
        __syncthreads();
        const int u = s_u;
        if (u >= NUNITS) break;

        const int tb = u >> 6;
        const int r6 = u & 63;
        const int kh = r6 & 1;
        const int nh = (r6 >> 1) & 1;
        const int rt = r6 >> 2;

        float acc[2][4][4];
#pragma unroll
        for (int mi = 0; mi < 2; mi++)
#pragma unroll
            for (int ni = 0; ni < 4; ni++)
#pragma unroll
                for (int q = 0; q < 4; q++) acc[mi][ni][q] = 0.0f;

        const uint4* pAh = g_Afh +
            ((size_t)(rt * 256 + kh * 128) * 8 + 2 * wm) * 32 + lane;
        const uint4* pAl = g_Afl +
            ((size_t)(rt * 256 + kh * 128) * 8 + 2 * wm) * 32 + lane;
        const uint4* pWh = g_Wfh +
            ((size_t)(tb * 256 + kh * 128) * 8 + nh * 4 + wn * 2) * 32 + lane;
        const uint4* pWl = g_Wfl +
            ((size_t)(tb * 256 + kh * 128) * 8 + nh * 4 + wn * 2) * 32 + lane;

#pragma unroll 2
        for (int kg = 0; kg < 128; kg++) {
            uint32_t ah[8], al[8], wh[8], wl[8];
            {
                uint4 v;
                v = pAh[0];  ah[0] = v.x; ah[1] = v.y; ah[2] = v.z; ah[3] = v.w;
                v = pAh[32]; ah[4] = v.x; ah[5] = v.y; ah[6] = v.z; ah[7] = v.w;
                v = pAl[0];  al[0] = v.x; al[1] = v.y; al[2] = v.z; al[3] = v.w;
                v = pAl[32]; al[4] = v.x; al[5] = v.y; al[6] = v.z; al[7] = v.w;
                v = pWh[0];  wh[0] = v.x; wh[1] = v.y; wh[2] = v.z; wh[3] = v.w;
                v = pWh[32]; wh[4] = v.x; wh[5] = v.y; wh[6] = v.z; wh[7] = v.w;
                v = pWl[0];  wl[0] = v.x; wl[1] = v.y; wl[2] = v.z; wl[3] = v.w;
                v = pWl[32]; wl[4] = v.x; wl[5] = v.y; wl[6] = v.z; wl[7] = v.w;
            }
            pAh += 256; pAl += 256; pWh += 256; pWl += 256;

#pragma unroll
            for (int mi = 0; mi < 2; mi++) {
#pragma unroll
                for (int ni = 0; ni < 4; ni++)
                    mma_bf16(acc[mi][ni], ah + mi * 4, wh + ni * 2);
#pragma unroll
                for (int ni = 0; ni < 4; ni++)
                    mma_bf16(acc[mi][ni], ah + mi * 4, wl + ni * 2);
            }
#pragma unroll
            for (int mi = 0; mi < 2; mi++)
#pragma unroll
                for (int ni = 0; ni < 4; ni++)
                    mma_bf16(acc[mi][ni], al + mi * 4, wh + ni * 2);
        }

        float* outp = (kh ? g_acc1 : g_acc0) + (size_t)tb * B_ * C_;
        const int r0 = rt * 128 + wm * 32 + (lane >> 2);
        const int c0 = nh * 64 + wn * 32 + (lane & 3) * 2;
#pragma unroll
        for (int mi = 0; mi < 2; mi++)
#pragma unroll
            for (int ni = 0; ni < 4; ni++) {
                int row = r0 + mi * 16, col = c0 + ni * 8;
                float2 v;
                v.x = acc[mi][ni][0]; v.y = acc[mi][ni][1];
                *(float2*)(outp + (size_t)row * C_ + col) = v;
                v.x = acc[mi][ni][2]; v.y = acc[mi][ni][3];
                *(float2*)(outp + (size_t)(row + 8) * C_ + col) = v;
            }
    }
}

// ---------------- combine: acc0+acc1+bias -> Phi/Plo (t<18) or g_h ---------
__global__ void combine_kernel(const float* __restrict__ Wk_b,
                               const float* __restrict__ pb1)
{
    const int per_t = B_ * C_ / 4;
    int i = blockIdx.x * 256 + threadIdx.x;
    int t = i / per_t;
    int r = i - t * per_t;
    int c = (r & 31) << 2;

    const float4 v0 = *((const float4*)g_acc0 + i);
    const float4 v1 = *((const float4*)g_acc1 + i);
    const float* bias = (t < T_) ? (Wk_b + t * C_) : pb1;
    float s[4];
    s[0] = v0.x + v1.x + __ldg(bias + c + 0);
    s[1] = v0.y + v1.y + __ldg(bias + c + 1);
    s[2] = v0.z + v1.z + __ldg(bias + c + 2);
    s[3] = v0.w + v1.w + __ldg(bias + c + 3);

    if (t < T_) {
        __nv_bfloat162 h0, h1, l0, l1;
        h0.x = __float2bfloat16(s[0]);
        l0.x = __float2bfloat16(s[0] - __bfloat162float(h0.x));
        h0.y = __float2bfloat16(s[1]);
        l0.y = __float2bfloat16(s[1] - __bfloat162float(h0.y));
        h1.x = __float2bfloat16(s[2]);
        l1.x = __float2bfloat16(s[2] - __bfloat162float(h1.x));
        h1.y = __float2bfloat16(s[3]);
        l1.y = __float2bfloat16(s[3] - __bfloat162float(h1.y));
        size_t off = (size_t)t * B_ * C_ + (size_t)r * 4;
        *(__nv_bfloat162*)(g_Phi + off)     = h0;
        *(__nv_bfloat162*)(g_Phi + off + 2) = h1;
        *(__nv_bfloat162*)(g_Plo + off)     = l0;
        *(__nv_bfloat162*)(g_Plo + off + 2) = l1;
    } else {
        float4 o; o.x = s[0]; o.y = s[1]; o.z = s[2]; o.w = s[3];
        *((float4*)g_h + r) = o;
    }
}

// ---------------- flash NCE: per-thread local logsumexp, deferred merge ----
#define FST 272                     // 128 bf16 + 16B pad
#define FTILE_ (128 * FST)          // 34816
#define FL_REDM (6 * FTILE_)
#define FL_REDL (FL_REDM + 1024)
#define FL_DIAG (FL_REDL + 1024)
#define FL_SMEM (FL_DIAG + 512)     // 211456 bytes

__global__ __launch_bounds__(256, 1) void flash_mma_kernel()
{
    extern __shared__ __align__(128) char smem[];
    const uint32_t sb = smem_u32(smem);
    float* red_m = (float*)(smem + FL_REDM);
    float* red_l = (float*)(smem + FL_REDL);
    float* diag  = (float*)(smem + FL_DIAG);

    const int rb = blockIdx.x, t = blockIdx.y;
    const int tid = threadIdx.x, lane = tid & 31, wid = tid >> 5;
    const int wm = wid >> 1, wn = wid & 1;      // warp tile 32 x 64

    const __nv_bfloat16* Ehi = g_Ehi + ((size_t)t * B_ + rb * 128) * C_;
    const __nv_bfloat16* Elo = g_Elo + ((size_t)t * B_ + rb * 128) * C_;
    const __nv_bfloat16* Phi = g_Phi + (size_t)t * B_ * C_;
    const __nv_bfloat16* Plo = g_Plo + (size_t)t * B_ * C_;

#pragma unroll
    for (int f = 0; f < 8; f++) {
        int id = tid + f * 256, r = id >> 4, ch = (id & 15) << 4;
        cp16(sb + r * FST + ch,          (const char*)Ehi + r * 256 + ch);
        cp16(sb + FTILE_ + r * FST + ch, (const char*)Elo + r * 256 + ch);
    }
    CP_COMMIT();
#pragma unroll
    for (int f = 0; f < 8; f++) {
        int id = tid + f * 256, r = id >> 4, ch = (id & 15) << 4;
        cp16(sb + 2 * FTILE_ + r * FST + ch, (const char*)Phi + r * 256 + ch);
        cp16(sb + 3 * FTILE_ + r * FST + ch, (const char*)Plo + r * 256 + ch);
    }
    CP_COMMIT();

    // per-thread local logsumexp state over the logits THIS thread owns
    float m_r[4], l_r[4];
#pragma unroll
    for (int r = 0; r < 4; r++) { m_r[r] = -3.0e38f; l_r[r] = 0.0f; }

    const int a_rr = wm * 32 + (lane & 15);
    const int a_kb = (lane >> 4) << 4;
    const int b_rr = wn * 64 + (lane & 7) + ((lane >> 4) << 3);
    const int b_kb = ((lane >> 3) & 1) << 4;
    const int row4 = lane >> 2;

    for (int kt = 0; kt < 16; kt++) {
        __syncthreads();   // everyone done reading the buffer we overwrite next
        if (kt + 1 < 16) {
            uint32_t kb = sb + (2 + ((kt + 1) & 1) * 2) * FTILE_;
            const char* sh = (const char*)Phi + (size_t)(kt + 1) * 128 * 256;
            const char* sl = (const char*)Plo + (size_t)(kt + 1) * 128 * 256;
#pragma unroll
            for (int f = 0; f < 8; f++) {
                int id = tid + f * 256, r = id >> 4, ch = (id & 15) << 4;
                cp16(kb + r * FST + ch,          sh + r * 256 + ch);
                cp16(kb + FTILE_ + r * FST + ch, sl + r * 256 + ch);
            }
            CP_COMMIT();
            CP_WAIT(1);
        } else {
            CP_WAIT(0);
        }
        __syncthreads();   // stage kt visible to all threads

        const uint32_t Qh = sb, Ql = sb + FTILE_;
        const uint32_t Kh = sb + (2 + (kt & 1) * 2) * FTILE_;
        const uint32_t Kl = Kh + FTILE_;

        float acc[2][8][4];
#pragma unroll
        for (int mi = 0; mi < 2; mi++)
#pragma unroll
            for (int ni = 0; ni < 8; ni++)
#pragma unroll
                for (int q = 0; q < 4; q++) acc[mi][ni][q] = 0.0f;

#pragma unroll
        for (int k16 = 0; k16 < 8; k16++) {
            uint32_t bh[16], bl[16];
#pragma unroll
            for (int g = 0; g < 4; g++) {
                ldmx4(bh + g * 4, Kh + (b_rr + g * 16) * FST + k16 * 32 + b_kb);
                ldmx4(bl + g * 4, Kl + (b_rr + g * 16) * FST + k16 * 32 + b_kb);
            }
#pragma unroll
            for (int mi = 0; mi < 2; mi++) {
                uint32_t a[4];
                ldmx4(a, Qh + (a_rr + mi * 16) * FST + k16 * 32 + a_kb);
#pragma unroll
                for (int ni = 0; ni < 8; ni++) mma_bf16(acc[mi][ni], a, bh + ni * 2);
#pragma unroll
                for (int ni = 0; ni < 8; ni++) mma_bf16(acc[mi][ni], a, bl + ni * 2);
            }
#pragma unroll
            for (int mi = 0; mi < 2; mi++) {
                uint32_t a[4];
                ldmx4(a, Ql + (a_rr + mi * 16) * FST + k16 * 32 + a_kb);
#pragma unroll
                for (int ni = 0; ni < 8; ni++) mma_bf16(acc[mi][ni], a, bh + ni * 2);
            }
        }

        // ---- per-thread local logsumexp update (no barriers, no shfl) ----
#pragma unroll
        for (int mi = 0; mi < 2; mi++)
#pragma unroll
            for (int h = 0; h < 2; h++) {
                const int r = mi * 2 + h;
                float m_loc = acc[mi][0][h * 2];
#pragma unroll
                for (int ni = 0; ni < 8; ni++) {
                    m_loc = fmaxf(m_loc, acc[mi][ni][h * 2]);
                    m_loc = fmaxf(m_loc, acc[mi][ni][h * 2 + 1]);
                }
                float mn = fmaxf(m_r[r], m_loc);
                float s = 0.0f;
#pragma unroll
                for (int ni = 0; ni < 8; ni++) {
                    s += __expf(acc[mi][ni][h * 2] - mn);
                    s += __expf(acc[mi][ni][h * 2 + 1] - mn);
                }
                l_r[r] = l_r[r] * __expf(m_r[r] - mn) + s;
                m_r[r] = mn;
            }

        if (kt == rb) {     // diagonal capture (raw logits)
#pragma unroll
            for (int mi = 0; mi < 2; mi++)
#pragma unroll
                for (int ni = 0; ni < 8; ni++)
#pragma unroll
                    for (int q = 0; q < 4; q++) {
                        int rl = wm * 32 + mi * 16 + row4 + (q >> 1) * 8;
                        int cl = wn * 64 + ni * 8 + (lane & 3) * 2 + (q & 1);
                        if (rl == cl) diag[rl] = acc[mi][ni][q];
                    }
        }
    }

    // ---- deferred merge: quad shfl, then cross-warp via smem ----
#pragma unroll
    for (int r = 0; r < 4; r++) {
#pragma unroll
        for (int o = 1; o <= 2; o <<= 1) {
            float mo = __shfl_xor_sync(0xffffffffu, m_r[r], o);
            float lo = __shfl_xor_sync(0xffffffffu, l_r[r], o);
            float mn = fmaxf(m_r[r], mo);
            l_r[r] = l_r[r] * __expf(m_r[r] - mn) + lo * __expf(mo - mn);
            m_r[r] = mn;
        }
    }
    if ((lane & 3) == 0) {
#pragma unroll
        for (int r = 0; r < 4; r++) {
            int rg = wm * 32 + (r >> 1) * 16 + row4 + (r & 1) * 8;
            red_m[rg * 2 + wn] = m_r[r];
            red_l[rg * 2 + wn] = l_r[r];
        }
    }
    __syncthreads();   // red_* and diag visible
    if (wn == 0 && (lane & 3) == 0) {
        float v = 0.0f;
#pragma unroll
        for (int r = 0; r < 4; r++) {
            int rg = wm * 32 + (r >> 1) * 16 + row4 + (r & 1) * 8;
            float m0 = red_m[rg * 2], m1 = red_m[rg * 2 + 1];
            float mn = fmaxf(m0, m1);
            float l = red_l[rg * 2] * __expf(m0 - mn)
                    + red_l[rg * 2 + 1] * __expf(m1 - mn);
            v += diag[rg] - (mn + logf(l));
        }
        atomicAdd(&g_nce, v);
    }
}

// ---------------- BatchNorm statistics -------------------------------------
__global__ void bnstat_kernel()
{
    const int c   = blockIdx.x;
    const int tid = threadIdx.x;
    float s = 0.0f, sq = 0.0f;
    for (int b = tid; b < B_; b += 256) {
        float v = g_h[(size_t)b * C_ + c];
        s += v;
        sq = fmaf(v, v, sq);
    }
    __shared__ float ss[256], sqq[256];
    ss[tid] = s; sqq[tid] = sq;
    __syncthreads();
    for (int st = 128; st > 0; st >>= 1) {
        if (tid < st) { ss[tid] += ss[tid + st]; sqq[tid] += sqq[tid + st]; }
        __syncthreads();
    }
    if (tid == 0) {
        float mean = ss[0] * (1.0f / B_);
        float var  = sqq[0] * (1.0f / B_) - mean * mean;
        g_mean[c] = mean;
        g_rstd[c] = rsqrtf(var + 1e-5f);
    }
}

// ---------------- projection head ------------------------------------------
__global__ void proj_kernel(const float* __restrict__ gamma,
                            const float* __restrict__ beta,
                            const float* __restrict__ pw2,
                            const float* __restrict__ pb2,
                            float* __restrict__ out)
{
    __shared__ float w2s[P_][132];
    __shared__ float hn[32][129];
    __shared__ float mg[C_], bg[C_];

    const int tid  = threadIdx.x;
    const int base = blockIdx.x * 32;

    for (int f = tid; f < P_ * C_; f += 256) {
        int p = f >> 7, c = f & 127;
        w2s[p][c] = pw2[f];
    }
    if (tid < C_) {
        float sc = g_rstd[tid] * gamma[tid];
        mg[tid] = sc;
        bg[tid] = beta[tid] - g_mean[tid] * sc;
    }
    __syncthreads();

    for (int f = tid; f < 32 * C_; f += 256) {
        int r = f >> 7, c = f & 127;
        float v = g_h[(size_t)(base + r) * C_ + c];
        v = v * mg[c] + bg[c];
        v = (v >= 0.0f) ? v : 0.01f * v;
        hn[r][c] = v;
    }
    __syncthreads();

    const int r  = tid >> 3;
    const int pg = (tid & 7) * 4;
    float accp[4];
#pragma unroll
    for (int p = 0; p < 4; p++) accp[p] = 0.0f;
    for (int c = 0; c < C_; c++) {
        float hv = hn[r][c];
#pragma unroll
        for (int p = 0; p < 4; p++)
            accp[p] = fmaf(hv, w2s[pg + p][c], accp[p]);
    }
#pragma unroll
    for (int p = 0; p < 4; p++)
        out[1 + (size_t)(base + r) * P_ + pg + p] = accp[p] + pb2[pg + p];

    if (blockIdx.x == 0 && tid == 0)
        out[0] = g_nce * (-1.0f / (float)(B_ * T_));
}

// ---------------- launch ---------------------------------------------------
extern "C" void kernel_launch(void* const* d_in, const int* in_sizes, int n_in,
                              void* d_out, int out_size)
{
    const float* z     = (const float*)d_in[0];
    const float* c_t   = (const float*)d_in[1];
    const float* Wk_w  = (const float*)d_in[2];
    const float* Wk_b  = (const float*)d_in[3];
    const float* pw1   = (const float*)d_in[4];
    const float* pb1   = (const float*)d_in[5];
    const float* gamma = (const float*)d_in[6];
    const float* beta  = (const float*)d_in[7];
    const float* pw2   = (const float*)d_in[8];
    const float* pb2   = (const float*)d_in[9];
    float* out = (float*)d_out;

    init_kernel<<<(B_ * C_ + 255) / 256, 256>>>(z);
    convA_kernel<<<4096, 256>>>(c_t);
    convW_kernel<<<4864, 256>>>(Wk_w, pw1);

    gemm_mma_kernel<<<NPCTAS, 256>>>();

    combine_kernel<<<NT * B_ * C_ / 4 / 256, 256>>>(Wk_b, pb1);

    cudaFuncSetAttribute(flash_mma_kernel,
                         cudaFuncAttributeMaxDynamicSharedMemorySize, FL_SMEM);
    flash_mma_kernel<<<dim3(B_ / 128, T_), 256, FL_SMEM>>>();

    bnstat_kernel<<<C_, 256>>>();
    proj_kernel<<<B_ / 32, 256>>>(gamma, beta, pw2, pb2, out);
}